// round 1
// baseline (speedup 1.0000x reference)
#include <cuda_runtime.h>
#include <cuda_bf16.h>
#include <math.h>

// ---------------------------------------------------------------------------
// MQA fp32 baseline pipeline:
//   1) q = x @ Wq^T            [2048,2048]
//   2) k = x @ Wk^T            [2048,128]
//   3) vT = (x @ Wv^T)^T       [128,2048]
//   4) scores[h] = (q_h @ k^T)/sqrt(128)   [16][2048][2048]
//   5) rowwise softmax in place
//   6) attn[:, h*128:(h+1)*128] = P[h] @ v  (v via vT as B in A@B^T)
//   7) out = attn @ Wo^T
// All fp32. Scratch in __device__ globals (no allocations).
// ---------------------------------------------------------------------------

#define DIM 2048
#define SEQ 2048
#define NHEADS 16
#define HDIM 128

__device__ float g_q[(long)SEQ * DIM];            // 16 MB
__device__ float g_k[(long)SEQ * HDIM];           // 1 MB
__device__ float g_vT[(long)HDIM * SEQ];          // 1 MB
__device__ float g_scores[(long)NHEADS * SEQ * SEQ]; // 268 MB
__device__ float g_attn[(long)SEQ * DIM];         // 16 MB

// Generic fp32 GEMM: C = alpha * A @ B^T
//   A: [M,K] row stride lda, plus aZ element offset per blockIdx.z
//   B: [N,K] row stride ldb, plus bZ per z
//   C: C[m*ldcM + n*ldcN] (+ cZ per z)
// Tiles: BM x BN, K-step BK, per-thread TM x TN. Double-buffered smem.
template <int BM, int BN, int BK, int TM, int TN>
__global__ void __launch_bounds__((BM / TM) * (BN / TN))
sgemm_abt(const float* __restrict__ A, int lda, long aZ,
          const float* __restrict__ B, int ldb, long bZ,
          float* __restrict__ C, long ldcM, long ldcN, long cZ,
          int M, int N, int K, float alpha)
{
    constexpr int THREADS = (BM / TM) * (BN / TN);
    constexpr int A_LD = (BM * BK) / (THREADS * 4);
    constexpr int B_LD = (BN * BK) / (THREADS * 4);
    constexpr int KC4 = BK / 4;

    __shared__ float As[2][BK][BM];
    __shared__ float Bs[2][BK][BN];

    const int tid = threadIdx.x;
    const int m0 = blockIdx.y * BM;
    const int n0 = blockIdx.x * BN;

    A += aZ * blockIdx.z;
    B += bZ * blockIdx.z;
    C += cZ * blockIdx.z;

    constexpr int TCOLS = BN / TN;
    const int tr = tid / TCOLS;
    const int tc = tid % TCOLS;

    float acc[TM][TN];
#pragma unroll
    for (int i = 0; i < TM; i++)
#pragma unroll
        for (int j = 0; j < TN; j++) acc[i][j] = 0.0f;

    // --- tile loaders (global -> smem, transposed to [k][m]) ---
    auto loadA = [&](int kt, int buf) {
#pragma unroll
        for (int i = 0; i < A_LD; i++) {
            int idx = tid + i * THREADS;
            int row = idx / KC4;
            int c4  = idx % KC4;
            float4 f = *reinterpret_cast<const float4*>(
                &A[(long)(m0 + row) * lda + kt + c4 * 4]);
            As[buf][c4 * 4 + 0][row] = f.x;
            As[buf][c4 * 4 + 1][row] = f.y;
            As[buf][c4 * 4 + 2][row] = f.z;
            As[buf][c4 * 4 + 3][row] = f.w;
        }
    };
    auto loadB = [&](int kt, int buf) {
#pragma unroll
        for (int i = 0; i < B_LD; i++) {
            int idx = tid + i * THREADS;
            int row = idx / KC4;
            int c4  = idx % KC4;
            float4 f = *reinterpret_cast<const float4*>(
                &B[(long)(n0 + row) * ldb + kt + c4 * 4]);
            Bs[buf][c4 * 4 + 0][row] = f.x;
            Bs[buf][c4 * 4 + 1][row] = f.y;
            Bs[buf][c4 * 4 + 2][row] = f.z;
            Bs[buf][c4 * 4 + 3][row] = f.w;
        }
    };

    loadA(0, 0);
    loadB(0, 0);
    __syncthreads();

    const int nk = K / BK;
    for (int kt = 1; kt <= nk; kt++) {
        const int cur = (kt - 1) & 1;
        const int nxt = kt & 1;
        if (kt < nk) {
            loadA(kt * BK, nxt);
            loadB(kt * BK, nxt);
        }
#pragma unroll
        for (int kk = 0; kk < BK; kk++) {
            float ar[TM], br[TN];
#pragma unroll
            for (int i = 0; i < TM; i++) ar[i] = As[cur][kk][tr * TM + i];
#pragma unroll
            for (int j = 0; j < TN; j++) br[j] = Bs[cur][kk][tc * TN + j];
#pragma unroll
            for (int i = 0; i < TM; i++)
#pragma unroll
                for (int j = 0; j < TN; j++) acc[i][j] += ar[i] * br[j];
        }
        __syncthreads();
    }

#pragma unroll
    for (int i = 0; i < TM; i++) {
        const long m = m0 + tr * TM + i;
#pragma unroll
        for (int j = 0; j < TN; j++) {
            const long n = n0 + tc * TN + j;
            C[m * ldcM + n * ldcN] = alpha * acc[i][j];
        }
    }
}

// Rowwise softmax over rows of length ncols (ncols = 2048, 256 threads/block).
__global__ void __launch_bounds__(256) softmax_rows(float* __restrict__ S, int ncols)
{
    __shared__ float sbufA[8];
    __shared__ float sbufB[8];
    float* row = S + (long)blockIdx.x * ncols;
    const int tid = threadIdx.x;
    const int nper = ncols / 256; // 8

    float vals[8];
    float lmax = -1e30f;
#pragma unroll
    for (int i = 0; i < 8; i++) {
        vals[i] = row[tid + i * 256];
        lmax = fmaxf(lmax, vals[i]);
    }
    // block max
#pragma unroll
    for (int o = 16; o > 0; o >>= 1)
        lmax = fmaxf(lmax, __shfl_xor_sync(0xffffffffu, lmax, o));
    if ((tid & 31) == 0) sbufA[tid >> 5] = lmax;
    __syncthreads();
    float rmax = fmaxf(fmaxf(fmaxf(sbufA[0], sbufA[1]), fmaxf(sbufA[2], sbufA[3])),
                       fmaxf(fmaxf(sbufA[4], sbufA[5]), fmaxf(sbufA[6], sbufA[7])));

    float lsum = 0.0f;
#pragma unroll
    for (int i = 0; i < 8; i++) {
        vals[i] = __expf(vals[i] - rmax);
        lsum += vals[i];
    }
#pragma unroll
    for (int o = 16; o > 0; o >>= 1)
        lsum += __shfl_xor_sync(0xffffffffu, lsum, o);
    if ((tid & 31) == 0) sbufB[tid >> 5] = lsum;
    __syncthreads();
    float rsum = (sbufB[0] + sbufB[1]) + (sbufB[2] + sbufB[3]) +
                 (sbufB[4] + sbufB[5]) + (sbufB[6] + sbufB[7]);
    const float inv = 1.0f / rsum;
#pragma unroll
    for (int i = 0; i < 8; i++) row[tid + i * 256] = vals[i] * inv;
    (void)nper;
}

extern "C" void kernel_launch(void* const* d_in, const int* in_sizes, int n_in,
                              void* d_out, int out_size)
{
    const float* x  = (const float*)d_in[0];
    const float* Wq = (const float*)d_in[1];
    const float* Wk = (const float*)d_in[2];
    const float* Wv = (const float*)d_in[3];
    const float* Wo = (const float*)d_in[4];
    float* out = (float*)d_out;

    float *q, *k, *vT, *sc, *at;
    cudaGetSymbolAddress((void**)&q,  g_q);
    cudaGetSymbolAddress((void**)&k,  g_k);
    cudaGetSymbolAddress((void**)&vT, g_vT);
    cudaGetSymbolAddress((void**)&sc, g_scores);
    cudaGetSymbolAddress((void**)&at, g_attn);

    const float inv_sqrt_d = 0.08838834764831845f; // 1/sqrt(128)

    // 1) q = x @ Wq^T   [2048,2048]
    {
        dim3 grid(DIM / 128, SEQ / 128, 1);
        sgemm_abt<128, 128, 16, 8, 8><<<grid, 256>>>(
            x, DIM, 0, Wq, DIM, 0, q, DIM, 1, 0, SEQ, DIM, DIM, 1.0f);
    }
    // 2) k = x @ Wk^T   [2048,128]
    {
        dim3 grid(HDIM / 64, SEQ / 64, 1);
        sgemm_abt<64, 64, 16, 4, 4><<<grid, 256>>>(
            x, DIM, 0, Wk, DIM, 0, k, HDIM, 1, 0, SEQ, HDIM, DIM, 1.0f);
    }
    // 3) vT = (x @ Wv^T)^T  -> stored [128,2048]
    {
        dim3 grid(HDIM / 64, SEQ / 64, 1);
        sgemm_abt<64, 64, 16, 4, 4><<<grid, 256>>>(
            x, DIM, 0, Wv, DIM, 0, vT, 1, SEQ, 0, SEQ, HDIM, DIM, 1.0f);
    }
    // 4) scores[h] = (q_h @ k^T) / sqrt(128)  for all 16 heads
    {
        dim3 grid(SEQ / 128, SEQ / 128, NHEADS);
        sgemm_abt<128, 128, 16, 8, 8><<<grid, 256>>>(
            q, DIM, HDIM,                 // A = q, head offset 128 per z
            k, HDIM, 0,                   // B = k
            sc, SEQ, 1, (long)SEQ * SEQ,  // C = scores[h]
            SEQ, SEQ, HDIM, inv_sqrt_d);
    }
    // 5) softmax rows (16 * 2048 rows)
    softmax_rows<<<NHEADS * SEQ, 256>>>(sc, SEQ);

    // 6) attn[:, h*128:+128] = P[h] @ v   (B = vT so A@B^T works)
    {
        dim3 grid(HDIM / 128, SEQ / 128, NHEADS);
        sgemm_abt<128, 128, 16, 8, 8><<<grid, 256>>>(
            sc, SEQ, (long)SEQ * SEQ,     // A = P[h]
            vT, SEQ, 0,                   // B = vT [128,2048]
            at, DIM, 1, HDIM,             // C col offset h*128
            SEQ, HDIM, SEQ, 1.0f);
    }
    // 7) out = attn @ Wo^T
    {
        dim3 grid(DIM / 128, SEQ / 128, 1);
        sgemm_abt<128, 128, 16, 8, 8><<<grid, 256>>>(
            at, DIM, 0, Wo, DIM, 0, out, DIM, 1, 0, SEQ, DIM, DIM, 1.0f);
    }
}

// round 3
// speedup vs baseline: 4.3729x; 4.3729x over previous
#include <cuda_runtime.h>
#include <cuda_bf16.h>
#include <cstdint>

#define DIM 2048
#define SEQ 2048
#define NHEADS 16
#define HDIM 128

#define NSTAGES 3
#define STAGE_BYTES 32768              // A tile 16KB + B tile 16KB
#define DSMEM_BYTES (1024 + NSTAGES * STAGE_BYTES)

// Arch-feature guard: tcgen05 only exists on 'a' targets.
#if defined(__CUDA_ARCH_FEAT_SM103_ALL) || defined(__CUDA_ARCH_FEAT_SM100_ALL) || defined(__CUDA_ARCH_FEAT_SM101_ALL)
#define HAS_TCGEN05 1
#else
#define HAS_TCGEN05 0
#endif

// ---------------------------------------------------------------------------
// Scratch (device globals; no allocations allowed)
// ---------------------------------------------------------------------------
__device__ __nv_bfloat16 g_xhi[(long)SEQ * DIM],  g_xlo[(long)SEQ * DIM];
__device__ __nv_bfloat16 g_Wqhi[(long)DIM * DIM], g_Wqlo[(long)DIM * DIM];
__device__ __nv_bfloat16 g_Wkhi[(long)HDIM * DIM], g_Wklo[(long)HDIM * DIM];
__device__ __nv_bfloat16 g_Wvhi[(long)HDIM * DIM], g_Wvlo[(long)HDIM * DIM];
__device__ __nv_bfloat16 g_Wohi[(long)DIM * DIM], g_Wolo[(long)DIM * DIM];
__device__ __nv_bfloat16 g_qhi[(long)SEQ * DIM],  g_qlo[(long)SEQ * DIM];
__device__ __nv_bfloat16 g_khi[(long)SEQ * HDIM], g_klo[(long)SEQ * HDIM];
__device__ __nv_bfloat16 g_vThi[(long)HDIM * SEQ], g_vTlo[(long)HDIM * SEQ];
__device__ float         g_scores[(long)NHEADS * SEQ * SEQ];
__device__ __nv_bfloat16 g_Phi[(long)NHEADS * SEQ * SEQ];
__device__ __nv_bfloat16 g_Plo[(long)NHEADS * SEQ * SEQ];
__device__ __nv_bfloat16 g_athi[(long)SEQ * DIM], g_atlo[(long)SEQ * DIM];

// ---------------------------------------------------------------------------
// PTX helpers
// ---------------------------------------------------------------------------
__device__ __forceinline__ uint32_t cvta_smem(const void* p) {
    uint32_t a;
    asm("{ .reg .u64 t; cvta.to.shared.u64 t, %1; cvt.u32.u64 %0, t; }"
        : "=r"(a) : "l"(p));
    return a;
}

__device__ __forceinline__ void cp16(uint32_t s, const void* g) {
    asm volatile("cp.async.cg.shared.global [%0], [%1], 16;" :: "r"(s), "l"(g));
}
__device__ __forceinline__ void cp_commit() { asm volatile("cp.async.commit_group;"); }
template <int N> __device__ __forceinline__ void cp_wait() {
    asm volatile("cp.async.wait_group %0;" :: "n"(N));
}

#if HAS_TCGEN05
__device__ __forceinline__ uint32_t elect1() {
    uint32_t p;
    asm volatile("{\n .reg .pred p;\n elect.sync _|p, 0xFFFFFFFF;\n selp.b32 %0, 1, 0, p;\n}"
                 : "=r"(p));
    return p;
}

#define TC_ALLOC(smem_addr, ncols) \
    asm volatile("tcgen05.alloc.cta_group::1.sync.aligned.shared::cta.b32 [%0], %1;" \
                 :: "r"(smem_addr), "r"(ncols) : "memory")
#define TC_DEALLOC(tmem, ncols) \
    asm volatile("tcgen05.dealloc.cta_group::1.sync.aligned.b32 %0, %1;" \
                 :: "r"(tmem), "r"(ncols))
#define TC_RELINQ() \
    asm volatile("tcgen05.relinquish_alloc_permit.cta_group::1.sync.aligned;")
#define TC_COMMIT(mbar) \
    asm volatile("tcgen05.commit.cta_group::1.mbarrier::arrive::one.shared::cluster.b64 [%0];" \
                 :: "r"(mbar) : "memory")
#define TC_FENCE_AFTER()  asm volatile("tcgen05.fence::after_thread_sync;" ::: "memory")
#define TC_FENCE_BEFORE() asm volatile("tcgen05.fence::before_thread_sync;" ::: "memory")
#define TC_WAIT_LD()      asm volatile("tcgen05.wait::ld.sync.aligned;" ::: "memory")

#define MBAR_INIT(mbar, cnt) \
    asm volatile("mbarrier.init.shared.b64 [%0], %1;" :: "r"(mbar), "r"(cnt) : "memory")

__device__ __forceinline__ void mbar_wait(uint32_t mbar, uint32_t parity) {
    uint32_t done;
    asm volatile(
        "{\n .reg .pred p;\n"
        " mbarrier.try_wait.parity.acquire.cta.shared::cta.b64 p, [%1], %2;\n"
        " selp.b32 %0, 1, 0, p;\n}"
        : "=r"(done) : "r"(mbar), "r"(parity) : "memory");
    if (!done) {
        asm volatile(
            "{\n .reg .pred P1;\n"
            "WL_%=:\n"
            " mbarrier.try_wait.parity.acquire.cta.shared::cta.b64 P1, [%0], %1, 0x989680;\n"
            " @P1 bra.uni WD_%=;\n"
            " bra.uni WL_%=;\n"
            "WD_%=:\n}"
            :: "r"(mbar), "r"(parity) : "memory");
    }
}

__device__ __forceinline__ void mma_bf16_ss(uint32_t d_tmem, uint64_t a_desc,
                                            uint64_t b_desc, uint32_t idesc,
                                            uint32_t enable_d) {
    asm volatile(
        "{\n .reg .pred p;\n setp.ne.u32 p, %4, 0;\n"
        " tcgen05.mma.cta_group::1.kind::f16 [%0], %1, %2, %3, {%5, %5, %5, %5}, p;\n}"
        :: "r"(d_tmem), "l"(a_desc), "l"(b_desc), "r"(idesc), "r"(enable_d), "r"(0u)
        : "memory");
}

__device__ __forceinline__ uint64_t make_desc(uint32_t addr) {
    return (uint64_t(2) << 61) | (uint64_t(1) << 46) | (uint64_t(64) << 32) |
           (uint64_t(1) << 16) | ((uint64_t)(addr >> 4) & 0x3FFF);
}

#define LDTM_X32(r, addr) \
    asm volatile( \
        "tcgen05.ld.sync.aligned.32x32b.x32.b32 " \
        "{%0, %1, %2, %3, %4, %5, %6, %7, " \
        " %8, %9, %10, %11, %12, %13, %14, %15, " \
        " %16, %17, %18, %19, %20, %21, %22, %23, " \
        " %24, %25, %26, %27, %28, %29, %30, %31}, [%32];" \
        : "=r"((r)[0]),  "=r"((r)[1]),  "=r"((r)[2]),  "=r"((r)[3]), \
          "=r"((r)[4]),  "=r"((r)[5]),  "=r"((r)[6]),  "=r"((r)[7]), \
          "=r"((r)[8]),  "=r"((r)[9]),  "=r"((r)[10]), "=r"((r)[11]), \
          "=r"((r)[12]), "=r"((r)[13]), "=r"((r)[14]), "=r"((r)[15]), \
          "=r"((r)[16]), "=r"((r)[17]), "=r"((r)[18]), "=r"((r)[19]), \
          "=r"((r)[20]), "=r"((r)[21]), "=r"((r)[22]), "=r"((r)[23]), \
          "=r"((r)[24]), "=r"((r)[25]), "=r"((r)[26]), "=r"((r)[27]), \
          "=r"((r)[28]), "=r"((r)[29]), "=r"((r)[30]), "=r"((r)[31]) \
        : "r"(addr))
#endif  // HAS_TCGEN05

#if !HAS_TCGEN05
__device__ __forceinline__ void ldmat_x4(uint32_t& r0, uint32_t& r1, uint32_t& r2,
                                         uint32_t& r3, uint32_t addr) {
    asm volatile("ldmatrix.sync.aligned.m8n8.x4.shared.b16 {%0,%1,%2,%3}, [%4];"
                 : "=r"(r0), "=r"(r1), "=r"(r2), "=r"(r3) : "r"(addr));
}
__device__ __forceinline__ void ldmat_x2(uint32_t& r0, uint32_t& r1, uint32_t addr) {
    asm volatile("ldmatrix.sync.aligned.m8n8.x2.shared.b16 {%0,%1}, [%2];"
                 : "=r"(r0), "=r"(r1) : "r"(addr));
}
__device__ __forceinline__ void hmma16816(float* d, const uint32_t* a, const uint32_t* b) {
    asm volatile(
        "mma.sync.aligned.m16n8k16.row.col.f32.bf16.bf16.f32 "
        "{%0,%1,%2,%3}, {%4,%5,%6,%7}, {%8,%9}, {%0,%1,%2,%3};"
        : "+f"(d[0]), "+f"(d[1]), "+f"(d[2]), "+f"(d[3])
        : "r"(a[0]), "r"(a[1]), "r"(a[2]), "r"(a[3]), "r"(b[0]), "r"(b[1]));
}
#endif

// ---------------------------------------------------------------------------
// Generic tensor-core GEMM:  C = alpha * (Ahi@Bhi^T + Alo@Bhi^T + Ahi@Blo^T)
//   A: [M,K] bf16 row stride lda (+aZ per z); B: [N,K] (+bZ per z)
//   C(m,n) at m*ldcM + n*ldcN (+cZ per z); fp32 or (hi,lo) bf16
// Tiles: 128x128, BK=64 (128B rows, SW128 swizzle), NSTAGES cp.async ring.
// Body: tcgen05 on 'a' targets, mma.sync HMMA otherwise. Same symbol.
// ---------------------------------------------------------------------------
template <bool OUT_F32>
__global__ void __launch_bounds__(256) tc_gemm(
    const __nv_bfloat16* __restrict__ Ahi, const __nv_bfloat16* __restrict__ Alo,
    long lda, long aZ,
    const __nv_bfloat16* __restrict__ Bhi, const __nv_bfloat16* __restrict__ Blo,
    long ldb, long bZ,
    float* __restrict__ Cf, __nv_bfloat16* __restrict__ Chi,
    __nv_bfloat16* __restrict__ Clo,
    long ldcM, long ldcN, long cZ, int K, float alpha)
{
    extern __shared__ char dsm[];

    const int tid = threadIdx.x;
    const int wid = tid >> 5;
    const int lane = tid & 31;
    const int m0 = blockIdx.y * 128;
    const int n0 = blockIdx.x * 128;

    Ahi += aZ * blockIdx.z;  Alo += aZ * blockIdx.z;
    Bhi += bZ * blockIdx.z;  Blo += bZ * blockIdx.z;
    const long coff = cZ * blockIdx.z;

    const uint32_t dbase = (cvta_smem(dsm) + 1023u) & ~1023u;
    float* sm = (float*)(((uintptr_t)dsm + 1023u) & ~(uintptr_t)1023u);

    const int nkPer = K / 64;
    const int nkt = nkPer * 3;

    auto load_tile = [&](int t, int s) {
        const int pass = t / nkPer;
        const int kk = t - pass * nkPer;
        const __nv_bfloat16* Asrc = (pass == 1) ? Alo : Ahi;
        const __nv_bfloat16* Bsrc = (pass == 2) ? Blo : Bhi;
        const long k0 = (long)kk * 64;
        const uint32_t sA = dbase + s * STAGE_BYTES;
        const uint32_t sB = sA + 16384;
#pragma unroll
        for (int i = 0; i < 4; i++) {
            const int idx = tid + i * 256;
            const int row = idx >> 3;
            const int c16 = idx & 7;
            const uint32_t off = row * 128 + c16 * 16;
            const uint32_t sw = off ^ ((off >> 3) & 0x70);
            cp16(sA + sw, Asrc + (long)(m0 + row) * lda + k0 + c16 * 8);
            cp16(sB + sw, Bsrc + (long)(n0 + row) * ldb + k0 + c16 * 8);
        }
    };

#if HAS_TCGEN05
    // =================== tcgen05 path (sm_103a cubin) ===================
    __shared__ uint64_t s_bar[NSTAGES + 1];
    __shared__ uint32_t s_tptr;

    if (wid == 0) {
        TC_ALLOC(cvta_smem(&s_tptr), 128);
        TC_RELINQ();
    }
    if (tid == 0) {
        for (int s = 0; s < NSTAGES + 1; s++)
            MBAR_INIT(cvta_smem(&s_bar[s]), 1);
    }
    __syncthreads();
    const uint32_t tmem = s_tptr;

    for (int t = 0; t < NSTAGES; t++) { load_tile(t, t); cp_commit(); }

    // idesc: dtype F32, a/b BF16 K-major, M=128, N=128
    const uint32_t idesc = (1u << 4) | (1u << 7) | (1u << 10) | (16u << 17) | (8u << 24);

    int ph[NSTAGES];
#pragma unroll
    for (int s = 0; s < NSTAGES; s++) ph[s] = 0;

    int s = 0;
    for (int t = 0; t < nkt; t++) {
        cp_wait<NSTAGES - 1>();
        __syncthreads();
        asm volatile("fence.proxy.async.shared::cta;" ::: "memory");
        if (wid == 0) {
            if (elect1()) {
                const uint32_t sA = dbase + s * STAGE_BYTES;
                const uint64_t ad = make_desc(sA);
                const uint64_t bd = make_desc(sA + 16384);
#pragma unroll
                for (int j = 0; j < 4; j++)
                    mma_bf16_ss(tmem, ad + j * 2, bd + j * 2, idesc,
                                (t | j) != 0 ? 1u : 0u);
                TC_COMMIT(cvta_smem(&s_bar[s]));
            }
        }
        if (t + NSTAGES < nkt) {
            mbar_wait(cvta_smem(&s_bar[s]), ph[s]);
            ph[s] ^= 1;
            load_tile(t + NSTAGES, s);
        }
        cp_commit();
        s++; if (s == NSTAGES) s = 0;
    }

    if (wid == 0) {
        if (elect1()) TC_COMMIT(cvta_smem(&s_bar[NSTAGES]));
    }
    mbar_wait(cvta_smem(&s_bar[NSTAGES]), 0);
    TC_FENCE_AFTER();

    // TMEM -> padded smem
    if (tid < 128) {
        const int w4 = tid >> 5;
#pragma unroll
        for (int c = 0; c < 4; c++) {
            uint32_t r[32];
            LDTM_X32(r, tmem + c * 32);
            TC_WAIT_LD();
            float* dst = sm + (w4 * 32 + lane) * 129 + c * 32;
#pragma unroll
            for (int j = 0; j < 32; j++) dst[j] = __uint_as_float(r[j]);
        }
        TC_FENCE_BEFORE();
    }
    __syncthreads();
    if (wid == 0) TC_DEALLOC(tmem, 128);

#else
    // =================== mma.sync HMMA fallback (plain sm_103) ===================
    const int wm = wid >> 1;            // 0..3 : 32 rows each
    const int wn = wid & 1;             // 0..1 : 64 cols each
    const int lq = lane & 15;

    float acc[2][8][4];
#pragma unroll
    for (int mt = 0; mt < 2; mt++)
#pragma unroll
        for (int nt = 0; nt < 8; nt++)
#pragma unroll
            for (int j = 0; j < 4; j++) acc[mt][nt][j] = 0.0f;

    for (int t = 0; t < NSTAGES; t++) { load_tile(t, t); cp_commit(); }

    int s = 0;
    for (int t = 0; t < nkt; t++) {
        cp_wait<NSTAGES - 1>();
        __syncthreads();
        const uint32_t sA = dbase + s * STAGE_BYTES;
        const uint32_t sB = sA + 16384;
#pragma unroll
        for (int kc = 0; kc < 4; kc++) {
            uint32_t af[2][4];
#pragma unroll
            for (int mt = 0; mt < 2; mt++) {
                const int row = wm * 32 + mt * 16 + (lane & 7) + ((lane >> 3) & 1) * 8;
                const uint32_t off = row * 128 + kc * 32 + (lane >> 4) * 16;
                ldmat_x4(af[mt][0], af[mt][1], af[mt][2], af[mt][3],
                         sA + (off ^ ((off >> 3) & 0x70)));
            }
            uint32_t bf[8][2];
#pragma unroll
            for (int nt = 0; nt < 8; nt++) {
                const int row = wn * 64 + nt * 8 + (lq & 7);
                const uint32_t off = row * 128 + kc * 32 + (lq >> 3) * 16;
                ldmat_x2(bf[nt][0], bf[nt][1], sB + (off ^ ((off >> 3) & 0x70)));
            }
#pragma unroll
            for (int mt = 0; mt < 2; mt++)
#pragma unroll
                for (int nt = 0; nt < 8; nt++)
                    hmma16816(acc[mt][nt], af[mt], bf[nt]);
        }
        __syncthreads();
        if (t + NSTAGES < nkt) load_tile(t + NSTAGES, s);
        cp_commit();
        s++; if (s == NSTAGES) s = 0;
    }

    // accumulators -> padded smem
    __syncthreads();
    {
        const int qr = lane >> 2;
        const int qc = (lane & 3) * 2;
#pragma unroll
        for (int mt = 0; mt < 2; mt++) {
#pragma unroll
            for (int nt = 0; nt < 8; nt++) {
                const int r0 = wm * 32 + mt * 16 + qr;
                const int c0 = wn * 64 + nt * 8 + qc;
                sm[r0 * 129 + c0]       = acc[mt][nt][0];
                sm[r0 * 129 + c0 + 1]   = acc[mt][nt][1];
                sm[(r0 + 8) * 129 + c0]     = acc[mt][nt][2];
                sm[(r0 + 8) * 129 + c0 + 1] = acc[mt][nt][3];
            }
        }
    }
    __syncthreads();
#endif

    // =================== common writeback ===================
    if (ldcN == 1) {
        for (int idx = tid; idx < 16384; idx += 256) {
            const int r = idx >> 7, c = idx & 127;
            const float v = sm[r * 129 + c] * alpha;
            const long o = coff + (long)(m0 + r) * ldcM + (long)(n0 + c);
            if (OUT_F32) {
                Cf[o] = v;
            } else {
                __nv_bfloat16 h = __float2bfloat16(v);
                Chi[o] = h;
                Clo[o] = __float2bfloat16(v - __bfloat162float(h));
            }
        }
    } else {
        for (int idx = tid; idx < 16384; idx += 256) {
            const int r = idx & 127, c = idx >> 7;
            const float v = sm[r * 129 + c] * alpha;
            const long o = coff + (long)(m0 + r) * ldcM + (long)(n0 + c) * ldcN;
            if (OUT_F32) {
                Cf[o] = v;
            } else {
                __nv_bfloat16 h = __float2bfloat16(v);
                Chi[o] = h;
                Clo[o] = __float2bfloat16(v - __bfloat162float(h));
            }
        }
    }
}

// ---------------------------------------------------------------------------
// fp32 -> (hi, lo) bf16 split
// ---------------------------------------------------------------------------
__global__ void __launch_bounds__(256) f32_to_hilo(
    const float* __restrict__ in, __nv_bfloat16* __restrict__ hi,
    __nv_bfloat16* __restrict__ lo, long n4)
{
    const long i = (long)blockIdx.x * 256 + threadIdx.x;
    if (i >= n4) return;
    const float4 v = reinterpret_cast<const float4*>(in)[i];
    __nv_bfloat16 h0 = __float2bfloat16(v.x);
    __nv_bfloat16 h1 = __float2bfloat16(v.y);
    __nv_bfloat16 h2 = __float2bfloat16(v.z);
    __nv_bfloat16 h3 = __float2bfloat16(v.w);
    __nv_bfloat162* hi2 = reinterpret_cast<__nv_bfloat162*>(hi);
    __nv_bfloat162* lo2 = reinterpret_cast<__nv_bfloat162*>(lo);
    hi2[i * 2 + 0] = __nv_bfloat162(h0, h1);
    hi2[i * 2 + 1] = __nv_bfloat162(h2, h3);
    lo2[i * 2 + 0] = __nv_bfloat162(__float2bfloat16(v.x - __bfloat162float(h0)),
                                    __float2bfloat16(v.y - __bfloat162float(h1)));
    lo2[i * 2 + 1] = __nv_bfloat162(__float2bfloat16(v.z - __bfloat162float(h2)),
                                    __float2bfloat16(v.w - __bfloat162float(h3)));
}

// ---------------------------------------------------------------------------
// Rowwise softmax: fp32 scores -> (hi, lo) bf16 probs
// ---------------------------------------------------------------------------
__global__ void __launch_bounds__(256) softmax_rows(
    const float* __restrict__ S, __nv_bfloat16* __restrict__ Phi,
    __nv_bfloat16* __restrict__ Plo)
{
    __shared__ float sbufA[8];
    __shared__ float sbufB[8];
    const long base = (long)blockIdx.x * SEQ;
    const int tid = threadIdx.x;

    float vals[8];
    float lmax = -1e30f;
#pragma unroll
    for (int i = 0; i < 8; i++) {
        vals[i] = S[base + tid + i * 256];
        lmax = fmaxf(lmax, vals[i]);
    }
#pragma unroll
    for (int o = 16; o > 0; o >>= 1)
        lmax = fmaxf(lmax, __shfl_xor_sync(0xffffffffu, lmax, o));
    if ((tid & 31) == 0) sbufA[tid >> 5] = lmax;
    __syncthreads();
    float rmax = fmaxf(fmaxf(fmaxf(sbufA[0], sbufA[1]), fmaxf(sbufA[2], sbufA[3])),
                       fmaxf(fmaxf(sbufA[4], sbufA[5]), fmaxf(sbufA[6], sbufA[7])));

    float lsum = 0.0f;
#pragma unroll
    for (int i = 0; i < 8; i++) {
        vals[i] = __expf(vals[i] - rmax);
        lsum += vals[i];
    }
#pragma unroll
    for (int o = 16; o > 0; o >>= 1)
        lsum += __shfl_xor_sync(0xffffffffu, lsum, o);
    if ((tid & 31) == 0) sbufB[tid >> 5] = lsum;
    __syncthreads();
    float rsum = (sbufB[0] + sbufB[1]) + (sbufB[2] + sbufB[3]) +
                 (sbufB[4] + sbufB[5]) + (sbufB[6] + sbufB[7]);
    const float inv = 1.0f / rsum;
#pragma unroll
    for (int i = 0; i < 8; i++) {
        const float v = vals[i] * inv;
        const __nv_bfloat16 h = __float2bfloat16(v);
        Phi[base + tid + i * 256] = h;
        Plo[base + tid + i * 256] = __float2bfloat16(v - __bfloat162float(h));
    }
}

// ---------------------------------------------------------------------------
extern "C" void kernel_launch(void* const* d_in, const int* in_sizes, int n_in,
                              void* d_out, int out_size)
{
    const float* x  = (const float*)d_in[0];
    const float* Wq = (const float*)d_in[1];
    const float* Wk = (const float*)d_in[2];
    const float* Wv = (const float*)d_in[3];
    const float* Wo = (const float*)d_in[4];
    float* out = (float*)d_out;

    __nv_bfloat16 *xhi, *xlo, *Wqhi, *Wqlo, *Wkhi, *Wklo, *Wvhi, *Wvlo, *Wohi, *Wolo;
    __nv_bfloat16 *qhi, *qlo, *khi, *klo, *vThi, *vTlo, *Phi, *Plo, *athi, *atlo;
    float* sc;
    cudaGetSymbolAddress((void**)&xhi, g_xhi);   cudaGetSymbolAddress((void**)&xlo, g_xlo);
    cudaGetSymbolAddress((void**)&Wqhi, g_Wqhi); cudaGetSymbolAddress((void**)&Wqlo, g_Wqlo);
    cudaGetSymbolAddress((void**)&Wkhi, g_Wkhi); cudaGetSymbolAddress((void**)&Wklo, g_Wklo);
    cudaGetSymbolAddress((void**)&Wvhi, g_Wvhi); cudaGetSymbolAddress((void**)&Wvlo, g_Wvlo);
    cudaGetSymbolAddress((void**)&Wohi, g_Wohi); cudaGetSymbolAddress((void**)&Wolo, g_Wolo);
    cudaGetSymbolAddress((void**)&qhi, g_qhi);   cudaGetSymbolAddress((void**)&qlo, g_qlo);
    cudaGetSymbolAddress((void**)&khi, g_khi);   cudaGetSymbolAddress((void**)&klo, g_klo);
    cudaGetSymbolAddress((void**)&vThi, g_vThi); cudaGetSymbolAddress((void**)&vTlo, g_vTlo);
    cudaGetSymbolAddress((void**)&Phi, g_Phi);   cudaGetSymbolAddress((void**)&Plo, g_Plo);
    cudaGetSymbolAddress((void**)&athi, g_athi); cudaGetSymbolAddress((void**)&atlo, g_atlo);
    cudaGetSymbolAddress((void**)&sc, g_scores);

    cudaFuncSetAttribute(tc_gemm<true>,  cudaFuncAttributeMaxDynamicSharedMemorySize, DSMEM_BYTES);
    cudaFuncSetAttribute(tc_gemm<false>, cudaFuncAttributeMaxDynamicSharedMemorySize, DSMEM_BYTES);

    const float inv_sqrt_d = 0.08838834764831845f;

    // splits of inputs
    f32_to_hilo<<<(SEQ * DIM / 4 + 255) / 256, 256>>>(x, xhi, xlo, (long)SEQ * DIM / 4);
    f32_to_hilo<<<(DIM * DIM / 4 + 255) / 256, 256>>>(Wq, Wqhi, Wqlo, (long)DIM * DIM / 4);
    f32_to_hilo<<<(HDIM * DIM / 4 + 255) / 256, 256>>>(Wk, Wkhi, Wklo, (long)HDIM * DIM / 4);
    f32_to_hilo<<<(HDIM * DIM / 4 + 255) / 256, 256>>>(Wv, Wvhi, Wvlo, (long)HDIM * DIM / 4);
    f32_to_hilo<<<(DIM * DIM / 4 + 255) / 256, 256>>>(Wo, Wohi, Wolo, (long)DIM * DIM / 4);

    // 1) q = x @ Wq^T  -> (qhi, qlo)
    tc_gemm<false><<<dim3(DIM / 128, SEQ / 128, 1), 256, DSMEM_BYTES>>>(
        xhi, xlo, DIM, 0, Wqhi, Wqlo, DIM, 0,
        nullptr, qhi, qlo, DIM, 1, 0, DIM, 1.0f);

    // 2) k = x @ Wk^T  [2048,128] -> (khi, klo)
    tc_gemm<false><<<dim3(1, SEQ / 128, 1), 256, DSMEM_BYTES>>>(
        xhi, xlo, DIM, 0, Wkhi, Wklo, DIM, 0,
        nullptr, khi, klo, HDIM, 1, 0, DIM, 1.0f);

    // 3) vT = (x @ Wv^T)^T  [128,2048] -> (vThi, vTlo)
    tc_gemm<false><<<dim3(1, SEQ / 128, 1), 256, DSMEM_BYTES>>>(
        xhi, xlo, DIM, 0, Wvhi, Wvlo, DIM, 0,
        nullptr, vThi, vTlo, 1, SEQ, 0, DIM, 1.0f);

    // 4) scores[h] = (q_h @ k^T) / sqrt(128)  (fp32)
    tc_gemm<true><<<dim3(SEQ / 128, SEQ / 128, NHEADS), 256, DSMEM_BYTES>>>(
        qhi, qlo, DIM, HDIM, khi, klo, HDIM, 0,
        sc, nullptr, nullptr, SEQ, 1, (long)SEQ * SEQ, HDIM, inv_sqrt_d);

    // 5) softmax -> (Phi, Plo)
    softmax_rows<<<NHEADS * SEQ, 256>>>(sc, Phi, Plo);

    // 6) attn[:, h*128:+128] = P[h] @ v  -> (athi, atlo)
    tc_gemm<false><<<dim3(1, SEQ / 128, NHEADS), 256, DSMEM_BYTES>>>(
        Phi, Plo, SEQ, (long)SEQ * SEQ, vThi, vTlo, SEQ, 0,
        nullptr, athi, atlo, DIM, 1, HDIM, SEQ, 1.0f);

    // 7) out = attn @ Wo^T  (fp32)
    tc_gemm<true><<<dim3(DIM / 128, SEQ / 128, 1), 256, DSMEM_BYTES>>>(
        athi, atlo, DIM, 0, Wohi, Wolo, DIM, 0,
        out, nullptr, nullptr, DIM, 1, 0, DIM, 1.0f);
}